// round 8
// baseline (speedup 1.0000x reference)
#include <cuda_runtime.h>
#include <math.h>

#define INSIZE     1024
#define NREFL      20
#define BATCH      32768
#define WARPS_PB   8
#define ROWS_PW    4
#define NBATCH     (BATCH / ROWS_PW)   // 8192 batches of 4 rows

// Scratch (no device allocs allowed)
__device__ float g_sigma[INSIZE];
__device__ float g_cu[NREFL];
__device__ float g_cv[NREFL];

// Packed fp32x2 FMA (Blackwell FFMA2) — one instruction, two fp32 FMAs.
__device__ __forceinline__ unsigned long long ffma2(unsigned long long a,
                                                    unsigned long long b,
                                                    unsigned long long c) {
    unsigned long long d;
    asm("fma.rn.f32x2 %0, %1, %2, %3;" : "=l"(d) : "l"(a), "l"(b), "l"(c));
    return d;
}

union F4U {
    float4 f;
    unsigned long long p[2];
    float s[4];
};

// ---------------------------------------------------------------------------
// Prep: sigma diagonal from p, and 2/||u||^2 per reflector.
// ---------------------------------------------------------------------------
__global__ void prep_kernel(const float* __restrict__ U,
                            const float* __restrict__ p,
                            const float* __restrict__ V) {
    int tid = threadIdx.x;                 // launched with 1024 threads
    if (tid < INSIZE) {
        float pv = p[tid];
        float s = 1.0f / (1.0f + expf(-pv));
        // 2*R*(sigmoid-0.5)+SIGMA_MEAN with R=0.2, SIGMA_MEAN=0.8
        g_sigma[tid] = 0.4f * s + 0.6f;
    }
    int w = tid >> 5;
    int lane = tid & 31;
    if (w < NREFL) {
        float su = 0.0f, sv = 0.0f;
        for (int j = lane; j < INSIZE; j += 32) {
            float uu = U[w * INSIZE + j]; su += uu * uu;
            float vv = V[w * INSIZE + j]; sv += vv * vv;
        }
        #pragma unroll
        for (int off = 16; off; off >>= 1) {
            su += __shfl_xor_sync(0xffffffffu, su, off);
            sv += __shfl_xor_sync(0xffffffffu, sv, off);
        }
        if (lane == 0) {
            g_cu[w] = 2.0f / su;
            g_cv[w] = 2.0f / sv;
        }
    }
}

// ---------------------------------------------------------------------------
// Main: persistent, 1 CTA/SM, rows resident in registers, reflectors in smem.
// ---------------------------------------------------------------------------
extern __shared__ float smem[];

__global__ void __launch_bounds__(256, 1)
spectral_kernel(const float* __restrict__ x,
                const float* __restrict__ U,
                const float* __restrict__ V,
                const float* __restrict__ bias,
                float* __restrict__ out) {
    float* sU    = smem;                      // 20*1024
    float* sV    = sU + NREFL * INSIZE;       // 20*1024
    float* sSig  = sV + NREFL * INSIZE;       // 1024
    float* sBias = sSig + INSIZE;             // 1024
    float* sCu   = sBias + INSIZE;            // 20
    float* sCv   = sCu + NREFL;               // 20

    const int tid = threadIdx.x;

    // Stage reflectors + sigma + bias (float4 copies)
    for (int i = tid; i < NREFL * INSIZE / 4; i += 256) {
        reinterpret_cast<float4*>(sU)[i] = reinterpret_cast<const float4*>(U)[i];
        reinterpret_cast<float4*>(sV)[i] = reinterpret_cast<const float4*>(V)[i];
    }
    if (tid < 256) {
        reinterpret_cast<float4*>(sSig)[tid]  = reinterpret_cast<const float4*>(g_sigma)[tid];
        reinterpret_cast<float4*>(sBias)[tid] = reinterpret_cast<const float4*>(bias)[tid];
    }
    if (tid < NREFL) { sCu[tid] = g_cu[tid]; sCv[tid] = g_cv[tid]; }
    __syncthreads();

    const int lane  = tid & 31;
    const int warp  = tid >> 5;
    const int gwarp = blockIdx.x * WARPS_PB + warp;
    const int nwarp = gridDim.x * WARPS_PB;

    for (int b = gwarp; b < NBATCH; b += nwarp) {
        const int row0 = b * ROWS_PW;

        // Load 4 rows, lane holds float4 elements {4*lane+128*j .. +3}
        F4U xr[ROWS_PW][8];
        #pragma unroll
        for (int r = 0; r < ROWS_PW; r++) {
            const float4* xp =
                reinterpret_cast<const float4*>(x + (size_t)(row0 + r) * INSIZE);
            #pragma unroll
            for (int j = 0; j < 8; j++) xr[r][j].f = xp[lane + 32 * j];
        }

        // ---- U phase: x <- x * H_0 * H_1 * ... * H_19 ----
        #pragma unroll 1
        for (int i = 0; i < NREFL; i++) {
            F4U uf[8];
            const float4* up = reinterpret_cast<const float4*>(sU + i * INSIZE);
            #pragma unroll
            for (int j = 0; j < 8; j++) uf[j].f = up[lane + 32 * j];
            const float c = sCu[i];
            #pragma unroll
            for (int r = 0; r < ROWS_PW; r++) {
                unsigned long long a0 = 0ull, a1 = 0ull;
                #pragma unroll
                for (int j = 0; j < 8; j++) {
                    a0 = ffma2(xr[r][j].p[0], uf[j].p[0], a0);
                    a1 = ffma2(xr[r][j].p[1], uf[j].p[1], a1);
                }
                F4U t; t.p[0] = a0; t.p[1] = a1;
                float d = (t.s[0] + t.s[2]) + (t.s[1] + t.s[3]);
                #pragma unroll
                for (int off = 16; off; off >>= 1)
                    d += __shfl_xor_sync(0xffffffffu, d, off);
                F4U na; na.s[0] = -c * d; na.s[1] = na.s[0];
                #pragma unroll
                for (int j = 0; j < 8; j++) {
                    xr[r][j].p[0] = ffma2(uf[j].p[0], na.p[0], xr[r][j].p[0]);
                    xr[r][j].p[1] = ffma2(uf[j].p[1], na.p[0], xr[r][j].p[1]);
                }
            }
        }

        // ---- diagonal sigma scale ----
        {
            const float4* sp = reinterpret_cast<const float4*>(sSig);
            #pragma unroll
            for (int j = 0; j < 8; j++) {
                float4 sg = sp[lane + 32 * j];
                #pragma unroll
                for (int r = 0; r < ROWS_PW; r++) {
                    xr[r][j].s[0] *= sg.x; xr[r][j].s[1] *= sg.y;
                    xr[r][j].s[2] *= sg.z; xr[r][j].s[3] *= sg.w;
                }
            }
        }

        // ---- V phase: x <- x * G_19 * G_18 * ... * G_0 ----
        #pragma unroll 1
        for (int i = NREFL - 1; i >= 0; i--) {
            F4U vf[8];
            const float4* vp = reinterpret_cast<const float4*>(sV + i * INSIZE);
            #pragma unroll
            for (int j = 0; j < 8; j++) vf[j].f = vp[lane + 32 * j];
            const float c = sCv[i];
            #pragma unroll
            for (int r = 0; r < ROWS_PW; r++) {
                unsigned long long a0 = 0ull, a1 = 0ull;
                #pragma unroll
                for (int j = 0; j < 8; j++) {
                    a0 = ffma2(xr[r][j].p[0], vf[j].p[0], a0);
                    a1 = ffma2(xr[r][j].p[1], vf[j].p[1], a1);
                }
                F4U t; t.p[0] = a0; t.p[1] = a1;
                float d = (t.s[0] + t.s[2]) + (t.s[1] + t.s[3]);
                #pragma unroll
                for (int off = 16; off; off >>= 1)
                    d += __shfl_xor_sync(0xffffffffu, d, off);
                F4U na; na.s[0] = -c * d; na.s[1] = na.s[0];
                #pragma unroll
                for (int j = 0; j < 8; j++) {
                    xr[r][j].p[0] = ffma2(vf[j].p[0], na.p[0], xr[r][j].p[0]);
                    xr[r][j].p[1] = ffma2(vf[j].p[1], na.p[0], xr[r][j].p[1]);
                }
            }
        }

        // ---- bias add + store ----
        #pragma unroll
        for (int r = 0; r < ROWS_PW; r++) {
            float4* op =
                reinterpret_cast<float4*>(out + (size_t)(row0 + r) * INSIZE);
            const float4* bp = reinterpret_cast<const float4*>(sBias);
            #pragma unroll
            for (int j = 0; j < 8; j++) {
                float4 v = xr[r][j].f;
                float4 bb = bp[lane + 32 * j];
                v.x += bb.x; v.y += bb.y; v.z += bb.z; v.w += bb.w;
                op[lane + 32 * j] = v;
            }
        }
    }
}

// ---------------------------------------------------------------------------
extern "C" void kernel_launch(void* const* d_in, const int* in_sizes, int n_in,
                              void* d_out, int out_size) {
    const float* x    = (const float*)d_in[0];
    const float* U    = (const float*)d_in[1];
    const float* p    = (const float*)d_in[2];
    const float* V    = (const float*)d_in[3];
    const float* bias = (const float*)d_in[4];
    float* out = (float*)d_out;

    (void)in_sizes; (void)n_in; (void)out_size;

    prep_kernel<<<1, 1024>>>(U, p, V);

    int nsm = 148;
    cudaDeviceGetAttribute(&nsm, cudaDevAttrMultiProcessorCount, 0);

    size_t smem_bytes =
        (size_t)(2 * NREFL * INSIZE + 2 * INSIZE + 2 * NREFL) * sizeof(float);
    cudaFuncSetAttribute(spectral_kernel,
                         cudaFuncAttributeMaxDynamicSharedMemorySize,
                         (int)smem_bytes);

    spectral_kernel<<<nsm, 256, smem_bytes>>>(x, U, V, bias, out);
}